// round 10
// baseline (speedup 1.0000x reference)
#include <cuda_runtime.h>
#include <cstdint>

#define EPSF 1e-6f
#define ONE_M_EPS (1.0f - 1e-6f)
#define NEG_LOG_EPS 13.815510557964274f      /* -log(1e-6)   */
#define NEG_LOG_1ME 1.0000005000002918e-06f  /* -log(1-1e-6) */
#define INV_TEMP 14.285714285714285f         /* 1/0.07       */

// ---------------- device scratch ----------------
__device__ float d_qk[8u * 1024u * 1024u];     // 32 MB sim matrix (qk dot products)
__device__ float d_rsum[8192], d_rsq[8192], d_rse[8192];   // per (b,l), reduced over s
__device__ float d_csum[8192], d_csq[8192], d_cse[8192];   // per (b,s), reduced over l
__device__ unsigned d_rmaxu[8192], d_cmaxu[8192];          // order-preserving-key float max
__device__ float d_sharp1[8192], d_sharp2[8192];
__device__ float d_rlog[8192], d_clog[8192];   // log sum exp denominators
__device__ double d_acc[8][8];   // per-b: 0 poscnt,1 negcnt,2 geopos,3 geoneg,4 loss1,5 loss2,6 loss3
__device__ double d_cacc[2];     // contrastive: pos sum, neg sum

// ---------------- helpers ----------------
__device__ __forceinline__ float warpSum(float v) {
#pragma unroll
    for (int o = 16; o > 0; o >>= 1) v += __shfl_down_sync(0xffffffffu, v, o);
    return v;
}
__device__ __forceinline__ float warpMax(float v) {
#pragma unroll
    for (int o = 16; o > 0; o >>= 1) v = fmaxf(v, __shfl_down_sync(0xffffffffu, v, o));
    return v;
}
// order-preserving float<->uint key (key 0 < key(any finite float))
__device__ __forceinline__ unsigned fkey(float f) {
    unsigned b = __float_as_uint(f);
    return (b & 0x80000000u) ? ~b : (b | 0x80000000u);
}
__device__ __forceinline__ float funkey(unsigned u) {
    return __uint_as_float((u & 0x80000000u) ? (u ^ 0x80000000u) : ~u);
}

// ---------------- zero accumulators ----------------
__global__ void k_zero() {
    int i = blockIdx.x * 1024 + threadIdx.x;
    if (i < 8192) {
        d_rsum[i] = 0.f; d_rsq[i] = 0.f; d_rse[i] = 0.f; d_rmaxu[i] = 0u;
        d_csum[i] = 0.f; d_csq[i] = 0.f; d_cse[i] = 0.f; d_cmaxu[i] = 0u;
    }
    if (i < 64) ((double*)d_acc)[i] = 0.0;
    if (i < 2) d_cacc[i] = 0.0;
}

// ---------------- GEMM + fused stats epilogue ----------------
__global__ __launch_bounds__(256) void k_gemm(const float* __restrict__ Q,
                                              const float* __restrict__ Kp) {
    __shared__ float sm[2 * 64 * 68];
    float* As = sm;
    float* Bs = sm + 64 * 68;
    int b = blockIdx.z;
    int l0 = blockIdx.y * 64;
    int s0 = blockIdx.x * 64;
    const float* Qb = Q + (size_t)b * 1024 * 128;
    const float* Kb = Kp + (size_t)b * 1024 * 128;
    int tid = threadIdx.x;
    int tx = tid & 15, ty = tid >> 4;
    int am = tid >> 4;
    int ac4 = tid & 15;
    int bnn = tid >> 2;
    int bcc = tid & 3;

    float acc[4][4] = {};
#pragma unroll
    for (int kc = 0; kc < 2; kc++) {
        int kbase = kc * 64;
#pragma unroll
        for (int it = 0; it < 4; it++) {
            int m = am + it * 16;
            float4 v = *(const float4*)(Qb + (size_t)(l0 + m) * 128 + kbase + ac4 * 4);
            *(float4*)(As + m * 68 + ac4 * 4) = v;
        }
#pragma unroll
        for (int it = 0; it < 4; it++) {
            int c4 = bcc + it * 4;
            float4 v = *(const float4*)(Kb + (size_t)(s0 + bnn) * 128 + kbase + c4 * 4);
            Bs[(4 * c4 + 0) * 68 + bnn] = v.x;
            Bs[(4 * c4 + 1) * 68 + bnn] = v.y;
            Bs[(4 * c4 + 2) * 68 + bnn] = v.z;
            Bs[(4 * c4 + 3) * 68 + bnn] = v.w;
        }
        __syncthreads();
#pragma unroll 16
        for (int kk = 0; kk < 64; kk++) {
            float4 bv = *(const float4*)(Bs + kk * 68 + tx * 4);
            float a0 = As[(4 * ty + 0) * 68 + kk];
            float a1 = As[(4 * ty + 1) * 68 + kk];
            float a2 = As[(4 * ty + 2) * 68 + kk];
            float a3 = As[(4 * ty + 3) * 68 + kk];
            acc[0][0] = fmaf(a0, bv.x, acc[0][0]);
            acc[0][1] = fmaf(a0, bv.y, acc[0][1]);
            acc[0][2] = fmaf(a0, bv.z, acc[0][2]);
            acc[0][3] = fmaf(a0, bv.w, acc[0][3]);
            acc[1][0] = fmaf(a1, bv.x, acc[1][0]);
            acc[1][1] = fmaf(a1, bv.y, acc[1][1]);
            acc[1][2] = fmaf(a1, bv.z, acc[1][2]);
            acc[1][3] = fmaf(a1, bv.w, acc[1][3]);
            acc[2][0] = fmaf(a2, bv.x, acc[2][0]);
            acc[2][1] = fmaf(a2, bv.y, acc[2][1]);
            acc[2][2] = fmaf(a2, bv.z, acc[2][2]);
            acc[2][3] = fmaf(a2, bv.w, acc[2][3]);
            acc[3][0] = fmaf(a3, bv.x, acc[3][0]);
            acc[3][1] = fmaf(a3, bv.y, acc[3][1]);
            acc[3][2] = fmaf(a3, bv.z, acc[3][2]);
            acc[3][3] = fmaf(a3, bv.w, acc[3][3]);
        }
        __syncthreads();
    }
#pragma unroll
    for (int i = 0; i < 4; i++) {
        float4 o = make_float4(acc[i][0], acc[i][1], acc[i][2], acc[i][3]);
        *(float4*)(d_qk + (size_t)(b * 1024 + l0 + 4 * ty + i) * 1024 + s0 + tx * 4) = o;
    }

    // ---- fused stats epilogue ----
    float rsum[4] = {0.f, 0.f, 0.f, 0.f}, rsq[4] = {0.f, 0.f, 0.f, 0.f};
    float rse[4] = {0.f, 0.f, 0.f, 0.f}, rmx[4] = {-1e30f, -1e30f, -1e30f, -1e30f};
    float csum[4] = {0.f, 0.f, 0.f, 0.f}, csq[4] = {0.f, 0.f, 0.f, 0.f};
    float cse[4] = {0.f, 0.f, 0.f, 0.f}, cmx[4] = {-1e30f, -1e30f, -1e30f, -1e30f};
#pragma unroll
    for (int i = 0; i < 4; i++) {
#pragma unroll
        for (int j = 0; j < 4; j++) {
            float x = acc[i][j];
            float e = expf(x * INV_TEMP);
            rsum[i] += x; rsq[i] = fmaf(x, x, rsq[i]); rse[i] += e; rmx[i] = fmaxf(rmx[i], x);
            csum[j] += x; csq[j] = fmaf(x, x, csq[j]); cse[j] += e; cmx[j] = fmaxf(cmx[j], x);
        }
    }
#pragma unroll
    for (int o = 1; o < 16; o <<= 1) {
#pragma unroll
        for (int i = 0; i < 4; i++) {
            rsum[i] += __shfl_xor_sync(0xffffffffu, rsum[i], o);
            rsq[i]  += __shfl_xor_sync(0xffffffffu, rsq[i], o);
            rse[i]  += __shfl_xor_sync(0xffffffffu, rse[i], o);
            rmx[i] = fmaxf(rmx[i], __shfl_xor_sync(0xffffffffu, rmx[i], o));
        }
    }
    if (tx == 0) {
#pragma unroll
        for (int i = 0; i < 4; i++) {
            int row = b * 1024 + l0 + 4 * ty + i;
            atomicAdd(&d_rsum[row], rsum[i]);
            atomicAdd(&d_rsq[row], rsq[i]);
            atomicAdd(&d_rse[row], rse[i]);
            atomicMax(&d_rmaxu[row], fkey(rmx[i]));
        }
    }
    float* SC = sm;
#pragma unroll
    for (int j = 0; j < 4; j++) {
        int c = 4 * tx + j;
        SC[0 * 1024 + ty * 64 + c] = csum[j];
        SC[1 * 1024 + ty * 64 + c] = csq[j];
        SC[2 * 1024 + ty * 64 + c] = cse[j];
        SC[3 * 1024 + ty * 64 + c] = cmx[j];
    }
    __syncthreads();
    if (tid < 64) {
        float s0v = 0.f, s1v = 0.f, s2v = 0.f, s3v = -1e30f;
#pragma unroll
        for (int k = 0; k < 16; k++) {
            s0v += SC[0 * 1024 + k * 64 + tid];
            s1v += SC[1 * 1024 + k * 64 + tid];
            s2v += SC[2 * 1024 + k * 64 + tid];
            s3v = fmaxf(s3v, SC[3 * 1024 + k * 64 + tid]);
        }
        int col = b * 1024 + s0 + tid;
        atomicAdd(&d_csum[col], s0v);
        atomicAdd(&d_csq[col], s1v);
        atomicAdd(&d_cse[col], s2v);
        atomicMax(&d_cmaxu[col], fkey(s3v));
    }
}

// ---------------- sharpness softmax (merged row+col; 16 blocks x 1024) ----------------
__global__ __launch_bounds__(1024) void k_sharp(float* __restrict__ out) {
    __shared__ float sh[32];
    int which = blockIdx.x >> 3;   // 0 = row (l over s), 1 = col (s over l)
    int b = blockIdx.x & 7;
    const float* smp = which ? d_csum : d_rsum;
    const float* sqp = which ? d_csq : d_rsq;
    const float* sep = which ? d_cse : d_rse;
    const unsigned* mxp = which ? d_cmaxu : d_rmaxu;
    float* sharp = which ? d_sharp1 : d_sharp2;
    float* lse = which ? d_clog : d_rlog;
    int i = b * 1024 + threadIdx.x;
    float smv = smp[i];
    float mean = smv * (1.f / 1024.f);
    float var = (sqp[i] - smv * smv * (1.f / 1024.f)) * (1.f / 1023.f);
    float sv = (funkey(mxp[i]) - mean) / sqrtf(fmaxf(var, 1e-30f));
    lse[i] = logf(sep[i]);
    int lane = threadIdx.x & 31, w = threadIdx.x >> 5;
    float m = warpMax(sv);
    if (lane == 0) sh[w] = m;
    __syncthreads();
    if (w == 0) { float x = sh[lane]; x = warpMax(x); if (lane == 0) sh[0] = x; }
    __syncthreads();
    float M = sh[0];
    __syncthreads();
    float e = expf(sv - M);
    float s = warpSum(e);
    if (lane == 0) sh[w] = s;
    __syncthreads();
    if (w == 0) { float x = sh[lane]; x = warpSum(x); if (lane == 0) sh[0] = x; }
    __syncthreads();
    float S = sh[0];
    float o = e / S;
    sharp[i] = o;
    if (which) out[i] = o;   // sharpness output = sharp1
}

// ---------------- main masked accumulation over (b,l,s) ----------------
// Issue-bound rewrite: vectorized loads; __logf for args in [0.25,0.75];
// gn path: clipped-low -> constant; unclipped small conf -> exact-rounded
// series for -log(fl(1-conf)); accurate logf only for d >= 0.05 (P~1e-6).
__global__ __launch_bounds__(256) void k_main(const int* __restrict__ label) {
    int b = blockIdx.y, l = blockIdx.x;
    int row = b * 1024 + l;
    const float* qrow = d_qk + (size_t)row * 1024;
    const int* lrow = label + (size_t)row * 1024;
    const float* clogb = d_clog + b * 1024;
    const float* sh1b = d_sharp1 + b * 1024;
    float logrs = d_rlog[row];
    float sh2 = d_sharp2[row];
    const float C0 = -logf(1.0f - 1e-6f);     // -log(fl(1-1e-6)) reference form
    const float T_LO = -13.815510557964274f;  // log(1e-6)

    int s0i = threadIdx.x * 4;
    float4 xv = *(const float4*)(qrow + s0i);
    int4 lv = *(const int4*)(lrow + s0i);
    float4 cv = *(const float4*)(clogb + s0i);
    float4 w1 = *(const float4*)(sh1b + s0i);
    float xs[4] = {xv.x, xv.y, xv.z, xv.w};
    int lb[4] = {lv.x, lv.y, lv.z, lv.w};
    float cs[4] = {cv.x, cv.y, cv.z, cv.w};
    float ws[4] = {w1.x, w1.y, w1.z, w1.w};

    float poscnt = 0.f, negcnt = 0.f, gp = 0.f, gn = 0.f, L1 = 0.f, NLL = 0.f, L3 = 0.f;
#pragma unroll
    for (int j = 0; j < 4; j++) {
        float x = xs[j];
        float t = fmaf(2.f * INV_TEMP, x, -cs[j] - logrs);
        float simc = fminf(fmaxf((1.f + x) * 0.5f, EPSF), ONE_M_EPS);
        if (lb[j] == 1) {
            poscnt += 1.f;
            gp += fminf(fmaxf(-t, NEG_LOG_1ME), NEG_LOG_EPS);  // -log(clip(conf))
            float nll = -__logf(simc);                          // simc ~ [0.25,0.75]
            L1 = fmaf(nll, ws[j], L1);
            NLL += nll;
        } else {
            negcnt += 1.f;
            if (t < T_LO) {
                gn += C0;  // conf clipped at 1e-6: constant -log(fl(1-1e-6))
            } else {
                float conf = fminf(__expf(t), ONE_M_EPS);
                float y = 1.0f - conf;   // fp32-rounded subtraction (reference form)
                float d = 1.0f - y;      // exact (Sterbenz): recovers rounded conf
                if (d < 0.05f) {
                    // -log(1-d) = d + d^2/2 + d^3/3 + d^4/4  (err < d^5/5)
                    gn += d * fmaf(d, fmaf(d, fmaf(d, 0.25f, 0.33333334f), 0.5f), 1.0f);
                } else {
                    gn -= logf(y);       // rare (P ~ 1e-6): accurate path
                }
            }
            float y3 = 1.0f - simc;      // ~ [0.25,0.75]
            L3 -= __logf(y3);
        }
    }
    __shared__ float sh[7][8];
    int lane = threadIdx.x & 31, w = threadIdx.x >> 5;
    poscnt = warpSum(poscnt); negcnt = warpSum(negcnt);
    gp = warpSum(gp); gn = warpSum(gn);
    L1 = warpSum(L1); NLL = warpSum(NLL); L3 = warpSum(L3);
    if (lane == 0) {
        sh[0][w] = poscnt; sh[1][w] = negcnt; sh[2][w] = gp; sh[3][w] = gn;
        sh[4][w] = L1; sh[5][w] = NLL; sh[6][w] = L3;
    }
    __syncthreads();
    if (threadIdx.x == 0) {
        float v[7];
#pragma unroll
        for (int k = 0; k < 7; k++) {
            float a = sh[k][0];
#pragma unroll
            for (int j = 1; j < 8; j++) a += sh[k][j];
            v[k] = a;
        }
        atomicAdd(&d_acc[b][0], (double)v[0]);
        atomicAdd(&d_acc[b][1], (double)v[1]);
        atomicAdd(&d_acc[b][2], (double)v[2]);
        atomicAdd(&d_acc[b][3], (double)v[3]);
        atomicAdd(&d_acc[b][4], (double)v[4]);
        atomicAdd(&d_acc[b][5], (double)(sh2 * v[5]));  // loss2 = sharp2[b,l]*sum(nll)
        atomicAdd(&d_acc[b][6], (double)v[6]);
    }
}

// ---------------- contrastive branch ----------------
__global__ __launch_bounds__(256) void k_cl(const float* __restrict__ q_cl,
                                            const float* __restrict__ cl_pos,
                                            const int* __restrict__ idx) {
    __shared__ float qn[8][128];
    __shared__ int sidx[8];
    int tid = threadIdx.x;
    if (tid < 8) sidx[tid] = idx[tid];
    __syncthreads();
    int w = tid >> 5, lane = tid & 31;
    {
        const float* qp = q_cl + ((size_t)w * 256 + sidx[w]) * 128;
        float4 v = ((const float4*)qp)[lane];
        float ss = v.x * v.x + v.y * v.y + v.z * v.z + v.w * v.w;
#pragma unroll
        for (int o = 16; o > 0; o >>= 1) ss += __shfl_xor_sync(0xffffffffu, ss, o);
        float inv = 1.f / fmaxf(sqrtf(ss), 1e-12f);
        ((float4*)&qn[w][0])[lane] = make_float4(v.x * inv, v.y * inv, v.z * inv, v.w * inv);
    }
    __syncthreads();
    int r = blockIdx.x * 256 + tid;  // all_k row 0..2047
    const float* kp;
    if (r < 8) {
        kp = cl_pos + ((size_t)r * 256 + sidx[r]) * 128;  // sel (positives)
    } else {
        int rr = r - 8;
        int n = rr / 255;
        int j = rr % 255 + 1;
        int jj = (j == sidx[n]) ? 0 : j;  // swapped
        kp = cl_pos + ((size_t)n * 256 + jj) * 128;
    }
    float dot[8] = {0.f, 0.f, 0.f, 0.f, 0.f, 0.f, 0.f, 0.f};
    float ksq = 0.f;
    const float4* kp4 = (const float4*)kp;
#pragma unroll 8
    for (int c = 0; c < 32; c++) {
        float4 kv = kp4[c];
        ksq = fmaf(kv.x, kv.x, fmaf(kv.y, kv.y, fmaf(kv.z, kv.z, fmaf(kv.w, kv.w, ksq))));
#pragma unroll
        for (int q = 0; q < 8; q++) {
            float4 qv = ((const float4*)qn[q])[c];
            dot[q] = fmaf(kv.x, qv.x, fmaf(kv.y, qv.y, fmaf(kv.z, qv.z, fmaf(kv.w, qv.w, dot[q]))));
        }
    }
    float kinv = 1.f / fmaxf(sqrtf(ksq), 1e-12f);
    float negsum = 0.f;
    if (r < 8) {
        float sim = fminf(fmaxf((1.f + dot[r] * kinv) * 0.5f, EPSF), ONE_M_EPS);
        atomicAdd(&d_cacc[0], (double)(-logf(sim)));
    } else {
#pragma unroll
        for (int q = 0; q < 8; q++) {
            float sim = fminf(fmaxf((1.f + dot[q] * kinv) * 0.5f, EPSF), ONE_M_EPS);
            float y = 1.0f - sim;       // fp32-rounded subtraction (reference form)
            negsum -= logf(y);
        }
    }
    __shared__ float sred[8];
    negsum = warpSum(negsum);
    if (lane == 0) sred[w] = negsum;
    __syncthreads();
    if (tid == 0) {
        float a = sred[0];
#pragma unroll
        for (int j = 1; j < 8; j++) a += sred[j];
        atomicAdd(&d_cacc[1], (double)a);
    }
}

// ---------------- finalize scalars + cl_pos_save ----------------
__global__ __launch_bounds__(1024) void k_final(const float* __restrict__ cl_pos,
                                                const int* __restrict__ idx,
                                                float* __restrict__ out) {
    int tid = threadIdx.x;
    int n = tid >> 7, c = tid & 127;
    out[8192 + tid] = cl_pos[((size_t)n * 256 + idx[n]) * 128 + c];
    if (tid == 0) {
        double gp = 0.0, gn = 0.0, ls = 0.0;
        for (int b = 0; b < 8; b++) {
            double pc = d_acc[b][0]; if (pc < 1.0) pc = 1.0;
            double nc = d_acc[b][1]; if (nc < 1.0) nc = 1.0;
            gp += d_acc[b][2] / pc;
            gn += d_acc[b][3] / nc;
            ls += 0.5 * (d_acc[b][4] + d_acc[b][5]) + d_acc[b][6] / nc;
        }
        gp *= 0.125; gn *= 0.125; ls *= 0.125;
        double loss_geo = gp + gn;
        double geo_comb = (0.5 * loss_geo + 0.5 * ls) * 0.5;  // W_SHARP, W_LOCAL
        double contrast = (d_cacc[0] * (1.0 / 8.0) + d_cacc[1] * (1.0 / 16320.0)) * 0.5;
        double lcl = contrast * 0.5;  // * (1 - W_LOCAL)
        out[9216] = (float)(geo_comb + lcl);  // total
        out[9217] = (float)gp;                // geo_pos_loss
        out[9218] = (float)gn;                // geo_neg_loss
        out[9219] = (float)ls;                // loss_sharp
        out[9220] = (float)lcl;               // loss_cl
    }
}

extern "C" void kernel_launch(void* const* d_in, const int* in_sizes, int n_in,
                              void* d_out, int out_size) {
    const float* q_geo   = (const float*)d_in[0];
    const float* q_cl    = (const float*)d_in[1];
    const float* geo_pos = (const float*)d_in[2];
    const float* cl_pos  = (const float*)d_in[3];
    const int*   label   = (const int*)d_in[4];
    const int*   idx     = (const int*)d_in[5];
    float* out = (float*)d_out;

    k_zero<<<8, 1024>>>();
    k_gemm<<<dim3(16, 16, 8), 256>>>(q_geo, geo_pos);
    k_sharp<<<16, 1024>>>(out);
    k_main<<<dim3(1024, 8), 256>>>(label);
    k_cl<<<8, 256>>>(q_cl, cl_pos, idx);
    k_final<<<1, 1024>>>(cl_pos, idx, out);
}

// round 11
// speedup vs baseline: 1.7093x; 1.7093x over previous
#include <cuda_runtime.h>
#include <cstdint>

#define EPSF 1e-6f
#define ONE_M_EPS (1.0f - 1e-6f)
#define NEG_LOG_EPS 13.815510557964274f      /* -log(1e-6)   */
#define NEG_LOG_1ME 1.0000005000002918e-06f  /* -log(1-1e-6) */
#define INV_TEMP 14.285714285714285f         /* 1/0.07       */

// ---------------- device scratch ----------------
__device__ float d_qk[8u * 1024u * 1024u];     // 32 MB sim matrix (qk dot products)
__device__ float d_rsum[8192], d_rsq[8192], d_rse[8192];   // per (b,l), reduced over s
__device__ float d_csum[8192], d_csq[8192], d_cse[8192];   // per (b,s), reduced over l
__device__ unsigned d_rmaxu[8192], d_cmaxu[8192];          // order-preserving-key float max
__device__ float d_sharp1[8192], d_sharp2[8192];
__device__ float d_rlog[8192], d_clog[8192];   // log sum exp denominators
__device__ double d_acc[8][8];   // per-b: 0 poscnt,1 negcnt,2 geopos,3 geoneg,4 loss1,5 loss2,6 loss3
__device__ double d_cacc[2];     // contrastive: pos sum, neg sum

// ---------------- helpers ----------------
__device__ __forceinline__ float warpSum(float v) {
#pragma unroll
    for (int o = 16; o > 0; o >>= 1) v += __shfl_down_sync(0xffffffffu, v, o);
    return v;
}
__device__ __forceinline__ float warpMax(float v) {
#pragma unroll
    for (int o = 16; o > 0; o >>= 1) v = fmaxf(v, __shfl_down_sync(0xffffffffu, v, o));
    return v;
}
// order-preserving float<->uint key (key 0 < key(any finite float))
__device__ __forceinline__ unsigned fkey(float f) {
    unsigned b = __float_as_uint(f);
    return (b & 0x80000000u) ? ~b : (b | 0x80000000u);
}
__device__ __forceinline__ float funkey(unsigned u) {
    return __uint_as_float((u & 0x80000000u) ? (u ^ 0x80000000u) : ~u);
}

// ---------------- zero accumulators ----------------
__global__ void k_zero() {
    int i = blockIdx.x * 1024 + threadIdx.x;
    if (i < 8192) {
        d_rsum[i] = 0.f; d_rsq[i] = 0.f; d_rse[i] = 0.f; d_rmaxu[i] = 0u;
        d_csum[i] = 0.f; d_csq[i] = 0.f; d_cse[i] = 0.f; d_cmaxu[i] = 0u;
    }
    if (i < 64) ((double*)d_acc)[i] = 0.0;
    if (i < 2) d_cacc[i] = 0.0;
}

// ---------------- GEMM + fused stats epilogue ----------------
__global__ __launch_bounds__(256) void k_gemm(const float* __restrict__ Q,
                                              const float* __restrict__ Kp) {
    __shared__ float sm[2 * 64 * 68];
    float* As = sm;
    float* Bs = sm + 64 * 68;
    int b = blockIdx.z;
    int l0 = blockIdx.y * 64;
    int s0 = blockIdx.x * 64;
    const float* Qb = Q + (size_t)b * 1024 * 128;
    const float* Kb = Kp + (size_t)b * 1024 * 128;
    int tid = threadIdx.x;
    int tx = tid & 15, ty = tid >> 4;
    int am = tid >> 4;
    int ac4 = tid & 15;
    int bnn = tid >> 2;
    int bcc = tid & 3;

    float acc[4][4] = {};
#pragma unroll
    for (int kc = 0; kc < 2; kc++) {
        int kbase = kc * 64;
#pragma unroll
        for (int it = 0; it < 4; it++) {
            int m = am + it * 16;
            float4 v = *(const float4*)(Qb + (size_t)(l0 + m) * 128 + kbase + ac4 * 4);
            *(float4*)(As + m * 68 + ac4 * 4) = v;
        }
#pragma unroll
        for (int it = 0; it < 4; it++) {
            int c4 = bcc + it * 4;
            float4 v = *(const float4*)(Kb + (size_t)(s0 + bnn) * 128 + kbase + c4 * 4);
            Bs[(4 * c4 + 0) * 68 + bnn] = v.x;
            Bs[(4 * c4 + 1) * 68 + bnn] = v.y;
            Bs[(4 * c4 + 2) * 68 + bnn] = v.z;
            Bs[(4 * c4 + 3) * 68 + bnn] = v.w;
        }
        __syncthreads();
#pragma unroll 16
        for (int kk = 0; kk < 64; kk++) {
            float4 bv = *(const float4*)(Bs + kk * 68 + tx * 4);
            float a0 = As[(4 * ty + 0) * 68 + kk];
            float a1 = As[(4 * ty + 1) * 68 + kk];
            float a2 = As[(4 * ty + 2) * 68 + kk];
            float a3 = As[(4 * ty + 3) * 68 + kk];
            acc[0][0] = fmaf(a0, bv.x, acc[0][0]);
            acc[0][1] = fmaf(a0, bv.y, acc[0][1]);
            acc[0][2] = fmaf(a0, bv.z, acc[0][2]);
            acc[0][3] = fmaf(a0, bv.w, acc[0][3]);
            acc[1][0] = fmaf(a1, bv.x, acc[1][0]);
            acc[1][1] = fmaf(a1, bv.y, acc[1][1]);
            acc[1][2] = fmaf(a1, bv.z, acc[1][2]);
            acc[1][3] = fmaf(a1, bv.w, acc[1][3]);
            acc[2][0] = fmaf(a2, bv.x, acc[2][0]);
            acc[2][1] = fmaf(a2, bv.y, acc[2][1]);
            acc[2][2] = fmaf(a2, bv.z, acc[2][2]);
            acc[2][3] = fmaf(a2, bv.w, acc[2][3]);
            acc[3][0] = fmaf(a3, bv.x, acc[3][0]);
            acc[3][1] = fmaf(a3, bv.y, acc[3][1]);
            acc[3][2] = fmaf(a3, bv.z, acc[3][2]);
            acc[3][3] = fmaf(a3, bv.w, acc[3][3]);
        }
        __syncthreads();
    }
#pragma unroll
    for (int i = 0; i < 4; i++) {
        float4 o = make_float4(acc[i][0], acc[i][1], acc[i][2], acc[i][3]);
        *(float4*)(d_qk + (size_t)(b * 1024 + l0 + 4 * ty + i) * 1024 + s0 + tx * 4) = o;
    }

    // ---- fused stats epilogue ----
    float rsum[4] = {0.f, 0.f, 0.f, 0.f}, rsq[4] = {0.f, 0.f, 0.f, 0.f};
    float rse[4] = {0.f, 0.f, 0.f, 0.f}, rmx[4] = {-1e30f, -1e30f, -1e30f, -1e30f};
    float csum[4] = {0.f, 0.f, 0.f, 0.f}, csq[4] = {0.f, 0.f, 0.f, 0.f};
    float cse[4] = {0.f, 0.f, 0.f, 0.f}, cmx[4] = {-1e30f, -1e30f, -1e30f, -1e30f};
#pragma unroll
    for (int i = 0; i < 4; i++) {
#pragma unroll
        for (int j = 0; j < 4; j++) {
            float x = acc[i][j];
            float e = expf(x * INV_TEMP);
            rsum[i] += x; rsq[i] = fmaf(x, x, rsq[i]); rse[i] += e; rmx[i] = fmaxf(rmx[i], x);
            csum[j] += x; csq[j] = fmaf(x, x, csq[j]); cse[j] += e; cmx[j] = fmaxf(cmx[j], x);
        }
    }
#pragma unroll
    for (int o = 1; o < 16; o <<= 1) {
#pragma unroll
        for (int i = 0; i < 4; i++) {
            rsum[i] += __shfl_xor_sync(0xffffffffu, rsum[i], o);
            rsq[i]  += __shfl_xor_sync(0xffffffffu, rsq[i], o);
            rse[i]  += __shfl_xor_sync(0xffffffffu, rse[i], o);
            rmx[i] = fmaxf(rmx[i], __shfl_xor_sync(0xffffffffu, rmx[i], o));
        }
    }
    if (tx == 0) {
#pragma unroll
        for (int i = 0; i < 4; i++) {
            int row = b * 1024 + l0 + 4 * ty + i;
            atomicAdd(&d_rsum[row], rsum[i]);
            atomicAdd(&d_rsq[row], rsq[i]);
            atomicAdd(&d_rse[row], rse[i]);
            atomicMax(&d_rmaxu[row], fkey(rmx[i]));
        }
    }
    float* SC = sm;
#pragma unroll
    for (int j = 0; j < 4; j++) {
        int c = 4 * tx + j;
        SC[0 * 1024 + ty * 64 + c] = csum[j];
        SC[1 * 1024 + ty * 64 + c] = csq[j];
        SC[2 * 1024 + ty * 64 + c] = cse[j];
        SC[3 * 1024 + ty * 64 + c] = cmx[j];
    }
    __syncthreads();
    if (tid < 64) {
        float s0v = 0.f, s1v = 0.f, s2v = 0.f, s3v = -1e30f;
#pragma unroll
        for (int k = 0; k < 16; k++) {
            s0v += SC[0 * 1024 + k * 64 + tid];
            s1v += SC[1 * 1024 + k * 64 + tid];
            s2v += SC[2 * 1024 + k * 64 + tid];
            s3v = fmaxf(s3v, SC[3 * 1024 + k * 64 + tid]);
        }
        int col = b * 1024 + s0 + tid;
        atomicAdd(&d_csum[col], s0v);
        atomicAdd(&d_csq[col], s1v);
        atomicAdd(&d_cse[col], s2v);
        atomicMax(&d_cmaxu[col], fkey(s3v));
    }
}

// ---------------- sharpness softmax (merged row+col; 16 blocks x 1024) ----------------
__global__ __launch_bounds__(1024) void k_sharp(float* __restrict__ out) {
    __shared__ float sh[32];
    int which = blockIdx.x >> 3;   // 0 = row (l over s), 1 = col (s over l)
    int b = blockIdx.x & 7;
    const float* smp = which ? d_csum : d_rsum;
    const float* sqp = which ? d_csq : d_rsq;
    const float* sep = which ? d_cse : d_rse;
    const unsigned* mxp = which ? d_cmaxu : d_rmaxu;
    float* sharp = which ? d_sharp1 : d_sharp2;
    float* lse = which ? d_clog : d_rlog;
    int i = b * 1024 + threadIdx.x;
    float smv = smp[i];
    float mean = smv * (1.f / 1024.f);
    float var = (sqp[i] - smv * smv * (1.f / 1024.f)) * (1.f / 1023.f);
    float sv = (funkey(mxp[i]) - mean) / sqrtf(fmaxf(var, 1e-30f));
    lse[i] = logf(sep[i]);
    int lane = threadIdx.x & 31, w = threadIdx.x >> 5;
    float m = warpMax(sv);
    if (lane == 0) sh[w] = m;
    __syncthreads();
    if (w == 0) { float x = sh[lane]; x = warpMax(x); if (lane == 0) sh[0] = x; }
    __syncthreads();
    float M = sh[0];
    __syncthreads();
    float e = expf(sv - M);
    float s = warpSum(e);
    if (lane == 0) sh[w] = s;
    __syncthreads();
    if (w == 0) { float x = sh[lane]; x = warpSum(x); if (lane == 0) sh[0] = x; }
    __syncthreads();
    float S = sh[0];
    float o = e / S;
    sharp[i] = o;
    if (which) out[i] = o;   // sharpness output = sharp1
}

// ---------------- main masked accumulation over (b,l,s) ----------------
// MLP-oriented rewrite: one WARP per l-row (8 rows/block, 1024 blocks).
// Each lane streams 8 float4 of qk + 8 int4 of label => deep independent
// load queue; warp-level reduction; per-row sh2*NLL scaling at warp scope;
// 8x fewer blocks, barriers, and contended atomics than before.
__global__ __launch_bounds__(256) void k_main(const int* __restrict__ label) {
    int b = blockIdx.y;
    int l0 = blockIdx.x * 8;
    int w = threadIdx.x >> 5;      // warp -> row l0 + w
    int lane = threadIdx.x & 31;
    int row = b * 1024 + l0 + w;
    const float4* qrow = (const float4*)(d_qk + (size_t)row * 1024);
    const int4* lrow = (const int4*)(label + (size_t)row * 1024);
    const float4* clog4 = (const float4*)(d_clog + b * 1024);
    const float4* sh14 = (const float4*)(d_sharp1 + b * 1024);
    float logrs = d_rlog[row];
    float sh2 = d_sharp2[row];
    const float C0 = -logf(1.0f - 1e-6f);     // -log(fl(1-1e-6)) reference form
    const float T_LO = -13.815510557964274f;  // log(1e-6)

    float poscnt = 0.f, negcnt = 0.f, gp = 0.f, gn = 0.f, L1 = 0.f, NLL = 0.f, L3 = 0.f;
#pragma unroll 4
    for (int k2 = 0; k2 < 8; k2++) {
        int idx = lane + 32 * k2;
        float4 xv = qrow[idx];
        int4 lv = lrow[idx];
        float4 cv = clog4[idx];
        float4 w1 = sh14[idx];
        float xs[4] = {xv.x, xv.y, xv.z, xv.w};
        int lb[4] = {lv.x, lv.y, lv.z, lv.w};
        float cs[4] = {cv.x, cv.y, cv.z, cv.w};
        float ws[4] = {w1.x, w1.y, w1.z, w1.w};
#pragma unroll
        for (int j = 0; j < 4; j++) {
            float x = xs[j];
            float t = fmaf(2.f * INV_TEMP, x, -cs[j] - logrs);
            float simc = fminf(fmaxf((1.f + x) * 0.5f, EPSF), ONE_M_EPS);
            if (lb[j] == 1) {
                poscnt += 1.f;
                gp += fminf(fmaxf(-t, NEG_LOG_1ME), NEG_LOG_EPS);  // -log(clip(conf))
                float nll = -__logf(simc);                          // simc ~ [0.25,0.75]
                L1 = fmaf(nll, ws[j], L1);
                NLL += nll;
            } else {
                negcnt += 1.f;
                if (t < T_LO) {
                    gn += C0;  // conf clipped at 1e-6: constant -log(fl(1-1e-6))
                } else {
                    float conf = fminf(__expf(t), ONE_M_EPS);
                    float y = 1.0f - conf;   // fp32-rounded subtraction (reference form)
                    float d = 1.0f - y;      // exact (Sterbenz): recovers rounded conf
                    if (d < 0.05f) {
                        // -log(1-d) = d + d^2/2 + d^3/3 + d^4/4  (err < d^5/5)
                        gn += d * fmaf(d, fmaf(d, fmaf(d, 0.25f, 0.33333334f), 0.5f), 1.0f);
                    } else {
                        gn -= logf(y);       // rare (P ~ 1e-6): accurate path
                    }
                }
                float y3 = 1.0f - simc;      // ~ [0.25,0.75]
                L3 -= __logf(y3);
            }
        }
    }
    // warp reduction; each warp owns one row -> scale NLL by its sh2 here
    poscnt = warpSum(poscnt); negcnt = warpSum(negcnt);
    gp = warpSum(gp); gn = warpSum(gn);
    L1 = warpSum(L1); NLL = warpSum(NLL); L3 = warpSum(L3);
    __shared__ float sh[8][7];
    if (lane == 0) {
        sh[w][0] = poscnt; sh[w][1] = negcnt; sh[w][2] = gp; sh[w][3] = gn;
        sh[w][4] = L1; sh[w][5] = sh2 * NLL; sh[w][6] = L3;
    }
    __syncthreads();
    if (threadIdx.x < 7) {
        int k = threadIdx.x;
        float a = sh[0][k];
#pragma unroll
        for (int j = 1; j < 8; j++) a += sh[j][k];
        atomicAdd(&d_acc[b][k], (double)a);
    }
}

// ---------------- contrastive branch ----------------
__global__ __launch_bounds__(256) void k_cl(const float* __restrict__ q_cl,
                                            const float* __restrict__ cl_pos,
                                            const int* __restrict__ idx) {
    __shared__ float qn[8][128];
    __shared__ int sidx[8];
    int tid = threadIdx.x;
    if (tid < 8) sidx[tid] = idx[tid];
    __syncthreads();
    int w = tid >> 5, lane = tid & 31;
    {
        const float* qp = q_cl + ((size_t)w * 256 + sidx[w]) * 128;
        float4 v = ((const float4*)qp)[lane];
        float ss = v.x * v.x + v.y * v.y + v.z * v.z + v.w * v.w;
#pragma unroll
        for (int o = 16; o > 0; o >>= 1) ss += __shfl_xor_sync(0xffffffffu, ss, o);
        float inv = 1.f / fmaxf(sqrtf(ss), 1e-12f);
        ((float4*)&qn[w][0])[lane] = make_float4(v.x * inv, v.y * inv, v.z * inv, v.w * inv);
    }
    __syncthreads();
    int r = blockIdx.x * 256 + tid;  // all_k row 0..2047
    const float* kp;
    if (r < 8) {
        kp = cl_pos + ((size_t)r * 256 + sidx[r]) * 128;  // sel (positives)
    } else {
        int rr = r - 8;
        int n = rr / 255;
        int j = rr % 255 + 1;
        int jj = (j == sidx[n]) ? 0 : j;  // swapped
        kp = cl_pos + ((size_t)n * 256 + jj) * 128;
    }
    float dot[8] = {0.f, 0.f, 0.f, 0.f, 0.f, 0.f, 0.f, 0.f};
    float ksq = 0.f;
    const float4* kp4 = (const float4*)kp;
#pragma unroll 8
    for (int c = 0; c < 32; c++) {
        float4 kv = kp4[c];
        ksq = fmaf(kv.x, kv.x, fmaf(kv.y, kv.y, fmaf(kv.z, kv.z, fmaf(kv.w, kv.w, ksq))));
#pragma unroll
        for (int q = 0; q < 8; q++) {
            float4 qv = ((const float4*)qn[q])[c];
            dot[q] = fmaf(kv.x, qv.x, fmaf(kv.y, qv.y, fmaf(kv.z, qv.z, fmaf(kv.w, qv.w, dot[q]))));
        }
    }
    float kinv = 1.f / fmaxf(sqrtf(ksq), 1e-12f);
    float negsum = 0.f;
    if (r < 8) {
        float sim = fminf(fmaxf((1.f + dot[r] * kinv) * 0.5f, EPSF), ONE_M_EPS);
        atomicAdd(&d_cacc[0], (double)(-logf(sim)));
    } else {
#pragma unroll
        for (int q = 0; q < 8; q++) {
            float sim = fminf(fmaxf((1.f + dot[q] * kinv) * 0.5f, EPSF), ONE_M_EPS);
            float y = 1.0f - sim;       // fp32-rounded subtraction (reference form)
            negsum -= logf(y);
        }
    }
    __shared__ float sred[8];
    negsum = warpSum(negsum);
    if (lane == 0) sred[w] = negsum;
    __syncthreads();
    if (tid == 0) {
        float a = sred[0];
#pragma unroll
        for (int j = 1; j < 8; j++) a += sred[j];
        atomicAdd(&d_cacc[1], (double)a);
    }
}

// ---------------- finalize scalars + cl_pos_save ----------------
__global__ __launch_bounds__(1024) void k_final(const float* __restrict__ cl_pos,
                                                const int* __restrict__ idx,
                                                float* __restrict__ out) {
    int tid = threadIdx.x;
    int n = tid >> 7, c = tid & 127;
    out[8192 + tid] = cl_pos[((size_t)n * 256 + idx[n]) * 128 + c];
    if (tid == 0) {
        double gp = 0.0, gn = 0.0, ls = 0.0;
        for (int b = 0; b < 8; b++) {
            double pc = d_acc[b][0]; if (pc < 1.0) pc = 1.0;
            double nc = d_acc[b][1]; if (nc < 1.0) nc = 1.0;
            gp += d_acc[b][2] / pc;
            gn += d_acc[b][3] / nc;
            ls += 0.5 * (d_acc[b][4] + d_acc[b][5]) + d_acc[b][6] / nc;
        }
        gp *= 0.125; gn *= 0.125; ls *= 0.125;
        double loss_geo = gp + gn;
        double geo_comb = (0.5 * loss_geo + 0.5 * ls) * 0.5;  // W_SHARP, W_LOCAL
        double contrast = (d_cacc[0] * (1.0 / 8.0) + d_cacc[1] * (1.0 / 16320.0)) * 0.5;
        double lcl = contrast * 0.5;  // * (1 - W_LOCAL)
        out[9216] = (float)(geo_comb + lcl);  // total
        out[9217] = (float)gp;                // geo_pos_loss
        out[9218] = (float)gn;                // geo_neg_loss
        out[9219] = (float)ls;                // loss_sharp
        out[9220] = (float)lcl;               // loss_cl
    }
}

extern "C" void kernel_launch(void* const* d_in, const int* in_sizes, int n_in,
                              void* d_out, int out_size) {
    const float* q_geo   = (const float*)d_in[0];
    const float* q_cl    = (const float*)d_in[1];
    const float* geo_pos = (const float*)d_in[2];
    const float* cl_pos  = (const float*)d_in[3];
    const int*   label   = (const int*)d_in[4];
    const int*   idx     = (const int*)d_in[5];
    float* out = (float*)d_out;

    k_zero<<<8, 1024>>>();
    k_gemm<<<dim3(16, 16, 8), 256>>>(q_geo, geo_pos);
    k_sharp<<<16, 1024>>>(out);
    k_main<<<dim3(128, 8), 256>>>(label);
    k_cl<<<8, 256>>>(q_cl, cl_pos, idx);
    k_final<<<1, 1024>>>(cl_pos, idx, out);
}